// round 7
// baseline (speedup 1.0000x reference)
#include <cuda_runtime.h>
#include <cuda_fp16.h>

// CapsuleLayer dynamic routing — BT=4, fp16 batch-pair-packed priors/probs.
// x: [256, 1152, 8] f32 ; W: [10, 1152, 8, 16] f32 ; out: [256, 10, 16] f32
#define NB 256
#define NC 10
#define NR 1152
#define IC 8
#define OC 16
#define THREADS 1024
#define BT 4
#define PSTR2 1154                  // P row stride in half2 units (≡2 mod 32)
#define P2_FLOATS (OC * PSTR2)      // 18464 4-byte units per pair-array
#define NUM_ITER 3

// SMEM floats (4B units):
//   Pp0 | pad4 | Pp1 | Ep0(1156) | Ep1(1156) | red2[32*65] | S[64] | V[64] | red[128] | aux[16]
#define SMEM_FLOATS (2 * P2_FLOATS + 4 + 2 * 1156 + 32 * 65 + 64 + 64 + 128 + 16)

extern "C" __global__ void __launch_bounds__(THREADS, 1)
caps_route_kernel(const float* __restrict__ x,
                  const float* __restrict__ W,
                  float* __restrict__ out)
{
    extern __shared__ float sm[];
    // pair p holds batches (b0+p) in .x and (b0+p+2) in .y
    __half2* Pp0  = reinterpret_cast<__half2*>(sm);
    __half2* Pp1  = reinterpret_cast<__half2*>(sm + P2_FLOATS + 4);
    __half2* Ep0  = reinterpret_cast<__half2*>(sm + 2 * P2_FLOATS + 4);
    __half2* Ep1  = Ep0 + 1156;
    float*   red2 = sm + 2 * P2_FLOATS + 4 + 2 * 1156;   // [32][65]
    float*   S    = red2 + 32 * 65;    // [b*16 + oc], b = 0..3
    float*   V    = S + 64;            // squashed outputs [b*16 + oc]
    float*   red  = V + 64;            // [4][32]
    float*   aux  = red + 128;

    const int tid  = threadIdx.x;
    const int lane = tid & 31;
    const int wid  = tid >> 5;

    const int b0 = blockIdx.x * BT;
    const int c  = blockIdx.y;

    const float4* Wc4 = reinterpret_cast<const float4*>(
                            W + (size_t)c * NR * IC * OC);

    // ============ Phase 1: priors (direct LDG W) + fused iter0 sums ==========
    // thread = (row_l = tid>>3, sub = (tid>>1)&3, p = tid&1); 9 rows/thread.
    // Each thread computes oc-quad sub*4.. for batches (b0+p) and (b0+p+2).
    {
        const int row_l = tid >> 3;
        const int sub   = (tid >> 1) & 3;
        const int p     = tid & 1;
        const float* xA = x + (size_t)(b0 + p)     * NR * IC;
        const float* xB = x + (size_t)(b0 + p + 2) * NR * IC;
        __half2*     Pp = p ? Pp1 : Pp0;

        float sA0 = 0.f, sA1 = 0.f, sA2 = 0.f, sA3 = 0.f;
        float sB0 = 0.f, sB1 = 0.f, sB2 = 0.f, sB3 = 0.f;

        #pragma unroll 3
        for (int it = 0; it < 9; ++it) {
            const int r = row_l + it * 128;
            const float4* wp = Wc4 + (size_t)r * 32 + sub;
            const float4 xa0 = reinterpret_cast<const float4*>(xA + r * IC)[0];
            const float4 xa1 = reinterpret_cast<const float4*>(xA + r * IC)[1];
            const float4 xc0 = reinterpret_cast<const float4*>(xB + r * IC)[0];
            const float4 xc1 = reinterpret_cast<const float4*>(xB + r * IC)[1];

            float aA0, aA1, aA2, aA3, aB0, aB1, aB2, aB3;
            {
                const float4 w0 = wp[0];
                const float4 w1 = wp[4];
                const float4 w2 = wp[8];
                const float4 w3 = wp[12];
                aA0 = xa0.x * w0.x; aA1 = xa0.x * w0.y; aA2 = xa0.x * w0.z; aA3 = xa0.x * w0.w;
                aB0 = xc0.x * w0.x; aB1 = xc0.x * w0.y; aB2 = xc0.x * w0.z; aB3 = xc0.x * w0.w;
                aA0 = fmaf(xa0.y, w1.x, aA0); aA1 = fmaf(xa0.y, w1.y, aA1);
                aA2 = fmaf(xa0.y, w1.z, aA2); aA3 = fmaf(xa0.y, w1.w, aA3);
                aB0 = fmaf(xc0.y, w1.x, aB0); aB1 = fmaf(xc0.y, w1.y, aB1);
                aB2 = fmaf(xc0.y, w1.z, aB2); aB3 = fmaf(xc0.y, w1.w, aB3);
                aA0 = fmaf(xa0.z, w2.x, aA0); aA1 = fmaf(xa0.z, w2.y, aA1);
                aA2 = fmaf(xa0.z, w2.z, aA2); aA3 = fmaf(xa0.z, w2.w, aA3);
                aB0 = fmaf(xc0.z, w2.x, aB0); aB1 = fmaf(xc0.z, w2.y, aB1);
                aB2 = fmaf(xc0.z, w2.z, aB2); aB3 = fmaf(xc0.z, w2.w, aB3);
                aA0 = fmaf(xa0.w, w3.x, aA0); aA1 = fmaf(xa0.w, w3.y, aA1);
                aA2 = fmaf(xa0.w, w3.z, aA2); aA3 = fmaf(xa0.w, w3.w, aA3);
                aB0 = fmaf(xc0.w, w3.x, aB0); aB1 = fmaf(xc0.w, w3.y, aB1);
                aB2 = fmaf(xc0.w, w3.z, aB2); aB3 = fmaf(xc0.w, w3.w, aB3);
            }
            {
                const float4 w4 = wp[16];
                const float4 w5 = wp[20];
                const float4 w6 = wp[24];
                const float4 w7 = wp[28];
                aA0 = fmaf(xa1.x, w4.x, aA0); aA1 = fmaf(xa1.x, w4.y, aA1);
                aA2 = fmaf(xa1.x, w4.z, aA2); aA3 = fmaf(xa1.x, w4.w, aA3);
                aB0 = fmaf(xc1.x, w4.x, aB0); aB1 = fmaf(xc1.x, w4.y, aB1);
                aB2 = fmaf(xc1.x, w4.z, aB2); aB3 = fmaf(xc1.x, w4.w, aB3);
                aA0 = fmaf(xa1.y, w5.x, aA0); aA1 = fmaf(xa1.y, w5.y, aA1);
                aA2 = fmaf(xa1.y, w5.z, aA2); aA3 = fmaf(xa1.y, w5.w, aA3);
                aB0 = fmaf(xc1.y, w5.x, aB0); aB1 = fmaf(xc1.y, w5.y, aB1);
                aB2 = fmaf(xc1.y, w5.z, aB2); aB3 = fmaf(xc1.y, w5.w, aB3);
                aA0 = fmaf(xa1.z, w6.x, aA0); aA1 = fmaf(xa1.z, w6.y, aA1);
                aA2 = fmaf(xa1.z, w6.z, aA2); aA3 = fmaf(xa1.z, w6.w, aA3);
                aB0 = fmaf(xc1.z, w6.x, aB0); aB1 = fmaf(xc1.z, w6.y, aB1);
                aB2 = fmaf(xc1.z, w6.z, aB2); aB3 = fmaf(xc1.z, w6.w, aB3);
                aA0 = fmaf(xa1.w, w7.x, aA0); aA1 = fmaf(xa1.w, w7.y, aA1);
                aA2 = fmaf(xa1.w, w7.z, aA2); aA3 = fmaf(xa1.w, w7.w, aA3);
                aB0 = fmaf(xc1.w, w7.x, aB0); aB1 = fmaf(xc1.w, w7.y, aB1);
                aB2 = fmaf(xc1.w, w7.z, aB2); aB3 = fmaf(xc1.w, w7.w, aB3);
            }

            const int ob = sub * 4;
            Pp[(ob + 0) * PSTR2 + r] = __floats2half2_rn(aA0, aB0);
            Pp[(ob + 1) * PSTR2 + r] = __floats2half2_rn(aA1, aB1);
            Pp[(ob + 2) * PSTR2 + r] = __floats2half2_rn(aA2, aB2);
            Pp[(ob + 3) * PSTR2 + r] = __floats2half2_rn(aA3, aB3);
            sA0 += aA0; sA1 += aA1; sA2 += aA2; sA3 += aA3;
            sB0 += aB0; sB1 += aB1; sB2 += aB2; sB3 += aB3;
        }

        // reduce iter0 sums over this warp's 4 rows (lane bits 3,4)
        #pragma unroll
        for (int off = 8; off <= 16; off <<= 1) {
            sA0 += __shfl_xor_sync(0xFFFFFFFFu, sA0, off);
            sA1 += __shfl_xor_sync(0xFFFFFFFFu, sA1, off);
            sA2 += __shfl_xor_sync(0xFFFFFFFFu, sA2, off);
            sA3 += __shfl_xor_sync(0xFFFFFFFFu, sA3, off);
            sB0 += __shfl_xor_sync(0xFFFFFFFFu, sB0, off);
            sB1 += __shfl_xor_sync(0xFFFFFFFFu, sB1, off);
            sB2 += __shfl_xor_sync(0xFFFFFFFFu, sB2, off);
            sB3 += __shfl_xor_sync(0xFFFFFFFFu, sB3, off);
        }
        if (lane < 8) {
            // lane = (p, sub); batch p -> A sums, batch p+2 -> B sums
            const int iA = p * 16 + sub * 4;
            const int iB = (p + 2) * 16 + sub * 4;
            float* row = red2 + wid * 65;
            row[iA + 0] = sA0; row[iA + 1] = sA1; row[iA + 2] = sA2; row[iA + 3] = sA3;
            row[iB + 0] = sB0; row[iB + 1] = sB1; row[iB + 2] = sB2; row[iB + 3] = sB3;
        }
    }
    __syncthreads();

    // ============ iter 0: squash from fused sums =============================
    const float inv_nr = 1.0f / (float)NR;
    if (tid < 64) {
        float s = 0.f;
        #pragma unroll
        for (int w2 = 0; w2 < 32; ++w2) s += red2[w2 * 65 + tid];
        float sv = s * inv_nr;
        float sq = sv * sv;
        #pragma unroll
        for (int off = 8; off > 0; off >>= 1)
            sq += __shfl_xor_sync(0xFFFFFFFFu, sq, off);   // within 16-lane group
        const float sc = sq / ((1.f + sq) * sqrtf(sq));
        V[tid] = sv * sc;
    }
    __syncthreads();

    // ============ Phase 2: routing iterations 1..2 ===========================
    const int  ra   = tid;
    const int  rb   = tid + THREADS;
    const bool hasb = (tid < NR - THREADS);   // tid < 128

    float La0 = 0.f, La1 = 0.f, La2 = 0.f, La3 = 0.f;
    float Lb0 = 0.f, Lb1 = 0.f, Lb2 = 0.f, Lb3 = 0.f;

    const int   wp_  = wid >> 4;              // WS: warp -> (pair, oc)
    const int   woc  = wid & 15;
    const __half2* wsP = (wp_ ? Pp1 : Pp0) + woc * PSTR2;
    const __half2* wsE = wp_ ? Ep1 : Ep0;

    for (int iter = 1; iter < NUM_ITER; ++iter) {
        // ---- delta logits (reads V of previous iteration) ----
        {
            const float4* V4 = reinterpret_cast<const float4*>(V);
            float da0 = 0.f, da1 = 0.f, da2 = 0.f, da3 = 0.f;
            float db0 = 0.f, db1 = 0.f, db2 = 0.f, db3 = 0.f;
            #pragma unroll
            for (int o4 = 0; o4 < 4; ++o4) {
                const float4 v0 = V4[o4];
                const float4 v1 = V4[4 + o4];
                const float4 v2 = V4[8 + o4];
                const float4 v3 = V4[12 + o4];
                const float v0a[4] = {v0.x, v0.y, v0.z, v0.w};
                const float v1a[4] = {v1.x, v1.y, v1.z, v1.w};
                const float v2a[4] = {v2.x, v2.y, v2.z, v2.w};
                const float v3a[4] = {v3.x, v3.y, v3.z, v3.w};
                #pragma unroll
                for (int j = 0; j < 4; ++j) {
                    const int oc = o4 * 4 + j;
                    const float2 f0 = __half22float2(Pp0[oc * PSTR2 + ra]);
                    const float2 f1 = __half22float2(Pp1[oc * PSTR2 + ra]);
                    da0 = fmaf(f0.x, v0a[j], da0);
                    da1 = fmaf(f1.x, v1a[j], da1);
                    da2 = fmaf(f0.y, v2a[j], da2);
                    da3 = fmaf(f1.y, v3a[j], da3);
                    if (hasb) {
                        const float2 g0 = __half22float2(Pp0[oc * PSTR2 + rb]);
                        const float2 g1 = __half22float2(Pp1[oc * PSTR2 + rb]);
                        db0 = fmaf(g0.x, v0a[j], db0);
                        db1 = fmaf(g1.x, v1a[j], db1);
                        db2 = fmaf(g0.y, v2a[j], db2);
                        db3 = fmaf(g1.y, v3a[j], db3);
                    }
                }
            }
            La0 += da0; La1 += da1; La2 += da2; La3 += da3;
            Lb0 += db0; Lb1 += db1; Lb2 += db2; Lb3 += db3;
        }

        // ---- softmax over r, 4 batches ----
        {
            float m0 = La0, m1 = La1, m2 = La2, m3 = La3;
            if (hasb) {
                m0 = fmaxf(m0, Lb0); m1 = fmaxf(m1, Lb1);
                m2 = fmaxf(m2, Lb2); m3 = fmaxf(m3, Lb3);
            }
            #pragma unroll
            for (int off = 16; off > 0; off >>= 1) {
                m0 = fmaxf(m0, __shfl_xor_sync(0xFFFFFFFFu, m0, off));
                m1 = fmaxf(m1, __shfl_xor_sync(0xFFFFFFFFu, m1, off));
                m2 = fmaxf(m2, __shfl_xor_sync(0xFFFFFFFFu, m2, off));
                m3 = fmaxf(m3, __shfl_xor_sync(0xFFFFFFFFu, m3, off));
            }
            if (lane == 0) {
                red[wid] = m0; red[32 + wid] = m1;
                red[64 + wid] = m2; red[96 + wid] = m3;
            }
            __syncthreads();
            if (wid < 4) {
                float v = red[wid * 32 + lane];
                #pragma unroll
                for (int off = 16; off > 0; off >>= 1)
                    v = fmaxf(v, __shfl_xor_sync(0xFFFFFFFFu, v, off));
                if (lane == 0) aux[wid] = v;
            }
            __syncthreads();
            m0 = aux[0]; m1 = aux[1]; m2 = aux[2]; m3 = aux[3];

            float s0, s1, s2, s3;
            {
                const float e0 = __expf(La0 - m0);
                const float e1 = __expf(La1 - m1);
                const float e2 = __expf(La2 - m2);
                const float e3 = __expf(La3 - m3);
                Ep0[ra] = __floats2half2_rn(e0, e2);
                Ep1[ra] = __floats2half2_rn(e1, e3);
                s0 = e0; s1 = e1; s2 = e2; s3 = e3;
                if (hasb) {
                    const float f0 = __expf(Lb0 - m0);
                    const float f1 = __expf(Lb1 - m1);
                    const float f2 = __expf(Lb2 - m2);
                    const float f3 = __expf(Lb3 - m3);
                    Ep0[rb] = __floats2half2_rn(f0, f2);
                    Ep1[rb] = __floats2half2_rn(f1, f3);
                    s0 += f0; s1 += f1; s2 += f2; s3 += f3;
                }
            }
            #pragma unroll
            for (int off = 16; off > 0; off >>= 1) {
                s0 += __shfl_xor_sync(0xFFFFFFFFu, s0, off);
                s1 += __shfl_xor_sync(0xFFFFFFFFu, s1, off);
                s2 += __shfl_xor_sync(0xFFFFFFFFu, s2, off);
                s3 += __shfl_xor_sync(0xFFFFFFFFu, s3, off);
            }
            if (lane == 0) {
                red[wid] = s0; red[32 + wid] = s1;
                red[64 + wid] = s2; red[96 + wid] = s3;
            }
            __syncthreads();
            if (wid < 4) {
                float v = red[wid * 32 + lane];
                #pragma unroll
                for (int off = 16; off > 0; off >>= 1)
                    v += __shfl_xor_sync(0xFFFFFFFFu, v, off);
                if (lane == 0) aux[4 + wid] = 1.0f / v;
            }
            __syncthreads();   // E + aux visible
        }

        // ---- weighted sum: warp (pair, oc), half2 scans give 2 batches ----
        {
            float ax = 0.f, ay = 0.f;
            #pragma unroll 4
            for (int rr = lane; rr < NR; rr += 32) {
                const float2 pp = __half22float2(wsP[rr]);
                const float2 ee = __half22float2(wsE[rr]);
                ax = fmaf(ee.x, pp.x, ax);
                ay = fmaf(ee.y, pp.y, ay);
            }
            #pragma unroll
            for (int off = 16; off > 0; off >>= 1) {
                ax += __shfl_xor_sync(0xFFFFFFFFu, ax, off);
                ay += __shfl_xor_sync(0xFFFFFFFFu, ay, off);
            }
            if (lane == 0) {
                S[wp_ * 16 + woc]       = ax;   // batch wp_
                S[(wp_ + 2) * 16 + woc] = ay;   // batch wp_ + 2
            }
        }
        __syncthreads();

        // ---- squash: warps 0,1 cover the 64 (batch, oc) slots ----
        if (wid < 2) {
            const int idx = wid * 32 + lane;
            float sv = S[idx] * aux[4 + (idx >> 4)];
            float sq = sv * sv;
            #pragma unroll
            for (int off = 8; off > 0; off >>= 1)
                sq += __shfl_xor_sync(0xFFFFFFFFu, sq, off);
            const float sc = sq / ((1.f + sq) * sqrtf(sq));
            V[idx] = sv * sc;
        }
        __syncthreads();
    }

    // ============ Phase 3: output ============================================
    if (tid < 4 * OC) {
        const int bb = tid >> 4;
        out[((size_t)(b0 + bb) * NC + c) * OC + (tid & 15)] = V[tid];
    }
}

extern "C" void kernel_launch(void* const* d_in, const int* in_sizes, int n_in,
                              void* d_out, int out_size)
{
    (void)in_sizes; (void)n_in; (void)out_size;
    const float* x = (const float*)d_in[0];
    const float* W = (const float*)d_in[1];
    float* out = (float*)d_out;

    static int smem_set = 0;
    const int smem_bytes = SMEM_FLOATS * sizeof(float);
    if (!smem_set) {
        cudaFuncSetAttribute(caps_route_kernel,
                             cudaFuncAttributeMaxDynamicSharedMemorySize,
                             smem_bytes);
        smem_set = 1;
    }

    dim3 grid(NB / BT, NC);
    caps_route_kernel<<<grid, THREADS, smem_bytes>>>(x, W, out);
}

// round 8
// speedup vs baseline: 1.2498x; 1.2498x over previous
#include <cuda_runtime.h>

// CapsuleLayer dynamic routing — BT=2, full-line W loads, split WS scans.
// x: [256, 1152, 8] f32 ; W: [10, 1152, 8, 16] f32 ; out: [256, 10, 16] f32
#define NB 256
#define NC 10
#define NR 1152
#define IC 8
#define OC 16
#define THREADS 1024
#define BT 2
#define PSTR 1154                 // P row stride (floats), ≡2 mod 32
#define P_FLOATS (OC * PSTR)      // 18464 ≡ 0 mod 32
#define NUM_ITER 3

// SMEM floats:
//   P0 | pad4 | P1 | E0[NR] | E1[NR] | red2[32*33] | S2[64] | V[32] | red[64] | aux[8]
#define SMEM_FLOATS (2 * P_FLOATS + 4 + 2 * NR + 32 * 33 + 64 + 32 + 64 + 8)

extern "C" __global__ void __launch_bounds__(THREADS, 1)
caps_route_kernel(const float* __restrict__ x,
                  const float* __restrict__ W,
                  float* __restrict__ out)
{
    extern __shared__ float sm[];
    float* P0   = sm;
    float* P1   = P0 + P_FLOATS + 4;      // +4: disjoint store banks vs P0
    float* E0   = P1 + P_FLOATS;
    float* E1   = E0 + NR;
    float* red2 = E1 + NR;                // [32][33]
    float* S2   = red2 + 32 * 33;         // [rhalf][b*16+oc]
    float* V    = S2 + 64;                // squashed outputs (16B aligned)
    float* red  = V + 32;
    float* aux  = red + 64;

    const int tid  = threadIdx.x;
    const int lane = tid & 31;
    const int wid  = tid >> 5;

    const int b0 = blockIdx.x * BT;
    const int c  = blockIdx.y;

    const float*  xb0 = x + (size_t)b0 * NR * IC;
    const float*  xb1 = xb0 + NR * IC;
    const float4* Wc4 = reinterpret_cast<const float4*>(
                            W + (size_t)c * NR * IC * OC);

    // ============ Phase 1: priors — full-line W loads, 1-level shfl merge ====
    // lane = rloc*8 + q ; q = qi*4 + sub. Warp-instr k loads 4 rows' full
    // 128B line (i-pair k). Thread handles i = 2k+qi for oc-quad sub, both
    // batches; shfl_xor(4) merges qi parities; qi picks which batch it stores.
    {
        const int rloc  = lane >> 3;
        const int q     = lane & 7;
        const int qi    = q >> 2;
        const int sub   = q & 3;
        const int rbase = wid * 4 + rloc;

        float sA0 = 0.f, sA1 = 0.f, sA2 = 0.f, sA3 = 0.f;   // iter0 sums b0
        float sB0 = 0.f, sB1 = 0.f, sB2 = 0.f, sB3 = 0.f;   // iter0 sums b1

        float*      Pst = qi ? P1 : P0;

        #pragma unroll 3
        for (int it = 0; it < 9; ++it) {
            const int r = rbase + it * 128;
            const float4* wp = Wc4 + (size_t)r * 32 + q;
            const float4 w0 = wp[0];        // i-pair 0: i = qi
            const float4 w1 = wp[8];        // i-pair 1: i = 2+qi
            const float4 w2 = wp[16];       // i-pair 2: i = 4+qi
            const float4 w3 = wp[24];       // i-pair 3: i = 6+qi
            const float4 xa0 = reinterpret_cast<const float4*>(xb0 + r * IC)[0];
            const float4 xa1 = reinterpret_cast<const float4*>(xb0 + r * IC)[1];
            const float4 xc0 = reinterpret_cast<const float4*>(xb1 + r * IC)[0];
            const float4 xc1 = reinterpret_cast<const float4*>(xb1 + r * IC)[1];

            const float xA0 = qi ? xa0.y : xa0.x;
            const float xA1 = qi ? xa0.w : xa0.z;
            const float xA2 = qi ? xa1.y : xa1.x;
            const float xA3 = qi ? xa1.w : xa1.z;
            const float xB0 = qi ? xc0.y : xc0.x;
            const float xB1 = qi ? xc0.w : xc0.z;
            const float xB2 = qi ? xc1.y : xc1.x;
            const float xB3 = qi ? xc1.w : xc1.z;

            float aA0, aA1, aA2, aA3, aB0, aB1, aB2, aB3;
            aA0 = xA0 * w0.x; aA1 = xA0 * w0.y; aA2 = xA0 * w0.z; aA3 = xA0 * w0.w;
            aB0 = xB0 * w0.x; aB1 = xB0 * w0.y; aB2 = xB0 * w0.z; aB3 = xB0 * w0.w;
            aA0 = fmaf(xA1, w1.x, aA0); aA1 = fmaf(xA1, w1.y, aA1);
            aA2 = fmaf(xA1, w1.z, aA2); aA3 = fmaf(xA1, w1.w, aA3);
            aB0 = fmaf(xB1, w1.x, aB0); aB1 = fmaf(xB1, w1.y, aB1);
            aB2 = fmaf(xB1, w1.z, aB2); aB3 = fmaf(xB1, w1.w, aB3);
            aA0 = fmaf(xA2, w2.x, aA0); aA1 = fmaf(xA2, w2.y, aA1);
            aA2 = fmaf(xA2, w2.z, aA2); aA3 = fmaf(xA2, w2.w, aA3);
            aB0 = fmaf(xB2, w2.x, aB0); aB1 = fmaf(xB2, w2.y, aB1);
            aB2 = fmaf(xB2, w2.z, aB2); aB3 = fmaf(xB2, w2.w, aB3);
            aA0 = fmaf(xA3, w3.x, aA0); aA1 = fmaf(xA3, w3.y, aA1);
            aA2 = fmaf(xA3, w3.z, aA2); aA3 = fmaf(xA3, w3.w, aA3);
            aB0 = fmaf(xB3, w3.x, aB0); aB1 = fmaf(xB3, w3.y, aB1);
            aB2 = fmaf(xB3, w3.z, aB2); aB3 = fmaf(xB3, w3.w, aB3);

            // merge i-parities (qi twins differ in lane bit 2)
            aA0 += __shfl_xor_sync(0xFFFFFFFFu, aA0, 4);
            aA1 += __shfl_xor_sync(0xFFFFFFFFu, aA1, 4);
            aA2 += __shfl_xor_sync(0xFFFFFFFFu, aA2, 4);
            aA3 += __shfl_xor_sync(0xFFFFFFFFu, aA3, 4);
            aB0 += __shfl_xor_sync(0xFFFFFFFFu, aB0, 4);
            aB1 += __shfl_xor_sync(0xFFFFFFFFu, aB1, 4);
            aB2 += __shfl_xor_sync(0xFFFFFFFFu, aB2, 4);
            aB3 += __shfl_xor_sync(0xFFFFFFFFu, aB3, 4);

            // qi=0 twin stores batch0, qi=1 twin stores batch1 (disjoint banks)
            const float v0 = qi ? aB0 : aA0;
            const float v1 = qi ? aB1 : aA1;
            const float v2 = qi ? aB2 : aA2;
            const float v3 = qi ? aB3 : aA3;
            const int ob = sub * 4;
            Pst[(ob + 0) * PSTR + r] = v0;
            Pst[(ob + 1) * PSTR + r] = v1;
            Pst[(ob + 2) * PSTR + r] = v2;
            Pst[(ob + 3) * PSTR + r] = v3;

            sA0 += aA0; sA1 += aA1; sA2 += aA2; sA3 += aA3;
            sB0 += aB0; sB1 += aB1; sB2 += aB2; sB3 += aB3;
        }

        // reduce iter0 sums over rloc (lane bits 3,4); qi twins hold duplicates
        #pragma unroll
        for (int off = 8; off <= 16; off <<= 1) {
            sA0 += __shfl_xor_sync(0xFFFFFFFFu, sA0, off);
            sA1 += __shfl_xor_sync(0xFFFFFFFFu, sA1, off);
            sA2 += __shfl_xor_sync(0xFFFFFFFFu, sA2, off);
            sA3 += __shfl_xor_sync(0xFFFFFFFFu, sA3, off);
            sB0 += __shfl_xor_sync(0xFFFFFFFFu, sB0, off);
            sB1 += __shfl_xor_sync(0xFFFFFFFFu, sB1, off);
            sB2 += __shfl_xor_sync(0xFFFFFFFFu, sB2, off);
            sB3 += __shfl_xor_sync(0xFFFFFFFFu, sB3, off);
        }
        if (lane < 4) {           // rloc=0, qi=0, sub=lane
            float* row = red2 + wid * 33;
            row[lane * 4 + 0] = sA0;  row[lane * 4 + 1] = sA1;
            row[lane * 4 + 2] = sA2;  row[lane * 4 + 3] = sA3;
            row[16 + lane * 4 + 0] = sB0;  row[16 + lane * 4 + 1] = sB1;
            row[16 + lane * 4 + 2] = sB2;  row[16 + lane * 4 + 3] = sB3;
        }
    }
    __syncthreads();

    // ============ iter 0: squash from fused sums =============================
    const float inv_nr = 1.0f / (float)NR;
    if (wid == 0) {
        float s = 0.f;
        #pragma unroll
        for (int w2 = 0; w2 < 32; ++w2) s += red2[w2 * 33 + lane];
        float sv = s * inv_nr;
        float sq = sv * sv;
        #pragma unroll
        for (int off = 8; off > 0; off >>= 1)
            sq += __shfl_xor_sync(0xFFFFFFFFu, sq, off);   // within 16-half
        const float sc = sq / ((1.f + sq) * sqrtf(sq));
        V[lane] = sv * sc;
    }
    __syncthreads();

    // ============ Phase 2: routing iterations 1..2 ===========================
    const int  ra   = tid;
    const int  rb   = tid + THREADS;
    const bool hasb = (tid < NR - THREADS);   // tid < 128

    float La0 = 0.f, La1 = 0.f;
    float Lb0 = 0.f, Lb1 = 0.f;

    // WS mapping: warp = (batch, oc-pair, r-half)
    const int wsbb = wid >> 4;
    const int wsop = (wid >> 1) & 7;
    const int wsrh = wid & 1;
    const float* wsP = (wsbb ? P1 : P0);
    const float* wsE = wsbb ? E1 : E0;
    const int woc0 = wsop * 2, woc1 = woc0 + 1;
    const int rst  = wsrh * (NR / 2);

    for (int iter = 1; iter < NUM_ITER; ++iter) {
        // ---- delta logits (reads V of previous iteration) ----
        {
            const float4* V4 = reinterpret_cast<const float4*>(V);
            float da0 = 0.f, da1 = 0.f, db0 = 0.f, db1 = 0.f;
            #pragma unroll
            for (int o4 = 0; o4 < 4; ++o4) {
                const float4 v0 = V4[o4];
                const float4 v1 = V4[4 + o4];
                const float* p0 = P0 + (o4 * 4) * PSTR;
                const float* p1 = P1 + (o4 * 4) * PSTR;
                da0 = fmaf(p0[0 * PSTR + ra], v0.x, da0);
                da0 = fmaf(p0[1 * PSTR + ra], v0.y, da0);
                da0 = fmaf(p0[2 * PSTR + ra], v0.z, da0);
                da0 = fmaf(p0[3 * PSTR + ra], v0.w, da0);
                da1 = fmaf(p1[0 * PSTR + ra], v1.x, da1);
                da1 = fmaf(p1[1 * PSTR + ra], v1.y, da1);
                da1 = fmaf(p1[2 * PSTR + ra], v1.z, da1);
                da1 = fmaf(p1[3 * PSTR + ra], v1.w, da1);
                if (hasb) {
                    db0 = fmaf(p0[0 * PSTR + rb], v0.x, db0);
                    db0 = fmaf(p0[1 * PSTR + rb], v0.y, db0);
                    db0 = fmaf(p0[2 * PSTR + rb], v0.z, db0);
                    db0 = fmaf(p0[3 * PSTR + rb], v0.w, db0);
                    db1 = fmaf(p1[0 * PSTR + rb], v1.x, db1);
                    db1 = fmaf(p1[1 * PSTR + rb], v1.y, db1);
                    db1 = fmaf(p1[2 * PSTR + rb], v1.z, db1);
                    db1 = fmaf(p1[3 * PSTR + rb], v1.w, db1);
                }
            }
            La0 += da0; La1 += da1;
            Lb0 += db0; Lb1 += db1;
        }

        // ---- softmax over r (both batches) ----
        {
            float m0 = La0, m1 = La1;
            if (hasb) { m0 = fmaxf(m0, Lb0); m1 = fmaxf(m1, Lb1); }
            #pragma unroll
            for (int off = 16; off > 0; off >>= 1) {
                m0 = fmaxf(m0, __shfl_xor_sync(0xFFFFFFFFu, m0, off));
                m1 = fmaxf(m1, __shfl_xor_sync(0xFFFFFFFFu, m1, off));
            }
            if (lane == 0) { red[wid] = m0; red[32 + wid] = m1; }
            __syncthreads();
            if (wid < 2) {
                float v = red[wid * 32 + lane];
                #pragma unroll
                for (int off = 16; off > 0; off >>= 1)
                    v = fmaxf(v, __shfl_xor_sync(0xFFFFFFFFu, v, off));
                if (lane == 0) aux[wid] = v;
            }
            __syncthreads();
            m0 = aux[0]; m1 = aux[1];

            float s0, s1;
            {
                const float ea0 = __expf(La0 - m0);
                const float ea1 = __expf(La1 - m1);
                E0[ra] = ea0; E1[ra] = ea1;
                s0 = ea0; s1 = ea1;
                if (hasb) {
                    const float eb0 = __expf(Lb0 - m0);
                    const float eb1 = __expf(Lb1 - m1);
                    E0[rb] = eb0; E1[rb] = eb1;
                    s0 += eb0; s1 += eb1;
                }
            }
            #pragma unroll
            for (int off = 16; off > 0; off >>= 1) {
                s0 += __shfl_xor_sync(0xFFFFFFFFu, s0, off);
                s1 += __shfl_xor_sync(0xFFFFFFFFu, s1, off);
            }
            if (lane == 0) { red[wid] = s0; red[32 + wid] = s1; }
            __syncthreads();
            if (wid < 2) {
                float v = red[wid * 32 + lane];
                #pragma unroll
                for (int off = 16; off > 0; off >>= 1)
                    v += __shfl_xor_sync(0xFFFFFFFFu, v, off);
                if (lane == 0) aux[2 + wid] = 1.0f / v;
            }
            __syncthreads();   // E + aux visible
        }

        // ---- weighted sum: warp (batch, oc-pair, r-half); E read once/2 oc --
        {
            const float* pc0 = wsP + woc0 * PSTR;
            const float* pc1 = wsP + woc1 * PSTR;
            float a0 = 0.f, a1 = 0.f;
            #pragma unroll 3
            for (int rr = rst + lane; rr < rst + NR / 2; rr += 32) {
                const float e = wsE[rr];
                a0 = fmaf(e, pc0[rr], a0);
                a1 = fmaf(e, pc1[rr], a1);
            }
            #pragma unroll
            for (int off = 16; off > 0; off >>= 1) {
                a0 += __shfl_xor_sync(0xFFFFFFFFu, a0, off);
                a1 += __shfl_xor_sync(0xFFFFFFFFu, a1, off);
            }
            if (lane == 0) {
                S2[wsrh * 32 + wsbb * 16 + woc0] = a0;
                S2[wsrh * 32 + wsbb * 16 + woc1] = a1;
            }
        }
        __syncthreads();

        // ---- squash (warp 0; lanes 0-15 b0, 16-31 b1) ----
        if (wid == 0) {
            float sv = (S2[lane] + S2[32 + lane]) * aux[2 + (lane >> 4)];
            float sq = sv * sv;
            #pragma unroll
            for (int off = 8; off > 0; off >>= 1)
                sq += __shfl_xor_sync(0xFFFFFFFFu, sq, off);
            const float sc = sq / ((1.f + sq) * sqrtf(sq));
            V[lane] = sv * sc;
        }
        __syncthreads();
    }

    // ============ Phase 3: output ============================================
    if (tid < 2 * OC) {
        const int obb = tid >> 4;
        out[((size_t)(b0 + obb) * NC + c) * OC + (tid & 15)] = V[tid];
    }
}

extern "C" void kernel_launch(void* const* d_in, const int* in_sizes, int n_in,
                              void* d_out, int out_size)
{
    (void)in_sizes; (void)n_in; (void)out_size;
    const float* x = (const float*)d_in[0];
    const float* W = (const float*)d_in[1];
    float* out = (float*)d_out;

    static int smem_set = 0;
    const int smem_bytes = SMEM_FLOATS * sizeof(float);
    if (!smem_set) {
        cudaFuncSetAttribute(caps_route_kernel,
                             cudaFuncAttributeMaxDynamicSharedMemorySize,
                             smem_bytes);
        smem_set = 1;
    }

    dim3 grid(NB / BT, NC);
    caps_route_kernel<<<grid, THREADS, smem_bytes>>>(x, W, out);
}